// round 2
// baseline (speedup 1.0000x reference)
#include <cuda_runtime.h>
#include <cooperative_groups.h>

namespace cg = cooperative_groups;

#define NSEQ 384
#define IND  350
#define G4   1024
#define ZSP  68
#define BSP  260

// ---------------- scratch (device globals) -----------------------------------
__device__ float g_xT[IND * NSEQ];          // x transposed [350][384]
__device__ float g_gx[2][NSEQ][G4];         // gate preactivations (incl. biases)
__device__ float g_HT[512 * NSEQ];          // h transposed [512][384]
__device__ float g_AB[NSEQ * 512];          // [384][A(256) | B(256)]
__device__ float g_W2T[256 * 256];          // W2 transposed [k][n]

// ---------------- 1) embedding gather -> xT ----------------------------------
__global__ __launch_bounds__(352) void embed_kernel(
    const int* __restrict__ wid, const int* __restrict__ tyid,
    const float* __restrict__ etab, const float* __restrict__ ttab)
{
    int t = blockIdx.x, d = threadIdx.x;
    if (d < IND) {
        float v = (d < 300) ? etab[wid[t] * 300 + d]
                            : ttab[tyid[t] * 50 + (d - 300)];
        g_xT[d * NSEQ + t] = v;
    }
}

// ---------------- 2) gx = x @ Wih^T + bih + bhh (both dirs) -------------------
__global__ __launch_bounds__(384) void gx_kernel(
    const float* __restrict__ Wih_f, const float* __restrict__ bih_f, const float* __restrict__ bhh_f,
    const float* __restrict__ Wih_b, const float* __restrict__ bih_b, const float* __restrict__ bhh_b)
{
    int dir = blockIdx.y;
    const float* Wih = dir ? Wih_b : Wih_f;
    const float* bi  = dir ? bih_b : bih_f;
    const float* bh  = dir ? bhh_b : bhh_f;
    int t = threadIdx.x;
    int G0 = blockIdx.x * 8;
    const float* wp[8];
#pragma unroll
    for (int g = 0; g < 8; g++) wp[g] = Wih + (G0 + g) * IND;
    float acc[8] = {0.f,0.f,0.f,0.f,0.f,0.f,0.f,0.f};
    for (int k = 0; k < IND; k++) {
        float xv = g_xT[k * NSEQ + t];
#pragma unroll
        for (int g = 0; g < 8; g++) acc[g] = fmaf(xv, wp[g][k], acc[g]);
    }
#pragma unroll
    for (int g = 0; g < 8; g++)
        g_gx[dir][t][G0 + g] = acc[g] + bi[G0 + g] + bh[G0 + g];
}

// ---------------- 3) W2 transpose --------------------------------------------
__global__ __launch_bounds__(256) void w2t_kernel(const float* __restrict__ W2)
{
    int k = blockIdx.x, n = threadIdx.x;
    g_W2T[k * 256 + n] = W2[n * 256 + k];
}

// ---------------- 4) BiLSTM: 2 clusters x 8 CTAs, Whh in registers -----------
__global__ void __cluster_dims__(8, 1, 1) __launch_bounds__(256, 1)
lstm_kernel(const float* __restrict__ Whh_f, const float* __restrict__ Whh_b)
{
    __shared__ __align__(16) float hb[2][256];
    __shared__ float psum[256];
    __shared__ float asum[128];

    cg::cluster_group cluster = cg::this_cluster();
    int rk  = (int)cluster.block_rank();
    int dir = blockIdx.x >> 3;
    const float* Whh = dir ? Whh_b : Whh_f;
    int tid  = threadIdx.x;
    int l    = tid & 127;
    int half = tid >> 7;
    // gate-row this thread-pair computes: gate = l>>5 (i,f,g,o), col = rk*32+(l&31)
    int G    = ((l >> 5) << 8) + (rk << 5) + (l & 31);

    float w[128];
    const float* wsrc = Whh + G * 256 + half * 128;
#pragma unroll
    for (int q = 0; q < 128; q += 4) {
        float4 v = *(const float4*)&wsrc[q];
        w[q] = v.x; w[q + 1] = v.y; w[q + 2] = v.z; w[q + 3] = v.w;
    }
    hb[0][tid] = 0.f;
    float c = 0.f;
    float* dst[8];
    if (tid < 32) {
#pragma unroll
        for (int pr = 0; pr < 8; pr++)
            dst[pr] = cluster.map_shared_rank(&hb[0][0], pr);
    }
    __syncthreads();
    cluster.sync();

    const float* gx = &g_gx[dir][0][0];
    for (int t = 0; t < NSEQ; t++) {
        int cur = t & 1;
        const float* h = &hb[cur][half * 128];
        float a0 = 0.f, a1 = 0.f, a2 = 0.f, a3 = 0.f;
#pragma unroll
        for (int q = 0; q < 128; q += 4) {
            float4 hv = *(const float4*)&h[q];
            a0 = fmaf(w[q],     hv.x, a0);
            a1 = fmaf(w[q + 1], hv.y, a1);
            a2 = fmaf(w[q + 2], hv.z, a2);
            a3 = fmaf(w[q + 3], hv.w, a3);
        }
        psum[tid] = (a0 + a1) + (a2 + a3);
        __syncthreads();
        int idx = dir ? (NSEQ - 1 - t) : t;
        if (tid < 128)
            asum[tid] = psum[tid] + psum[tid + 128] + gx[idx * G4 + G];
        __syncthreads();
        if (tid < 32) {
            float iv = 1.f / (1.f + __expf(-asum[tid]));
            float fv = 1.f / (1.f + __expf(-asum[32 + tid]));
            float gv = tanhf(asum[64 + tid]);
            float ov = 1.f / (1.f + __expf(-asum[96 + tid]));
            c = fv * c + iv * gv;
            float hn = ov * tanhf(c);
            int col = (rk << 5) + tid;
            g_HT[(dir * 256 + col) * NSEQ + idx] = hn;
            int nxtoff = ((cur ^ 1) << 8) + col;
#pragma unroll
            for (int pr = 0; pr < 8; pr++)
                dst[pr][nxtoff] = hn;
        }
        cluster.sync();
    }
}

// ---------------- 5) A|B = h @ [W1a|W1b]^T ------------------------------------
__global__ __launch_bounds__(384) void ab_kernel(const float* __restrict__ W1)
{
    int t = threadIdx.x;
    int f0 = blockIdx.x * 8;
    const float* wp[8];
#pragma unroll
    for (int g = 0; g < 8; g++) {
        int f = f0 + g;
        wp[g] = (f < 256) ? (W1 + f * 1024) : (W1 + (f - 256) * 1024 + 512);
    }
    float acc[8] = {0.f,0.f,0.f,0.f,0.f,0.f,0.f,0.f};
    for (int k = 0; k < 512; k++) {
        float hv = g_HT[k * NSEQ + t];
#pragma unroll
        for (int g = 0; g < 8; g++) acc[g] = fmaf(hv, wp[g][k], acc[g]);
    }
#pragma unroll
    for (int g = 0; g < 8; g++) g_AB[t * 512 + f0 + g] = acc[g];
}

// ---------------- 6) fused pair MLP ------------------------------------------
// block = (one i) x (64 j) x (all 256 n). smem floats:
#define SM_W2 (64 * BSP)            // 16640
#define SM_Z  (SM_W2 + 16 * 256)    // 20736
#define SM_A  (SM_Z + 16 * ZSP)     // 21824
#define SM_TOT (SM_A + 256)         // 22080 floats = 88320 B

__global__ __launch_bounds__(256, 2) void pair_kernel(
    const float* __restrict__ b1, const float* __restrict__ b2,
    const float* __restrict__ Wf, const float* __restrict__ bf,
    float* __restrict__ out)
{
    extern __shared__ float sm[];
    float* Bsm  = sm;               // [64][BSP]  (reused as y later)
    float* w2sm = sm + SM_W2;       // [16][256]  (reused as WfT later)
    float* zsm  = sm + SM_Z;        // [16][ZSP]
    float* Asm  = sm + SM_A;        // [256] A_i + b1

    int tid = threadIdx.x;
    int i  = blockIdx.y;
    int j0 = blockIdx.x * 64;

#pragma unroll
    for (int it = 0; it < 16; it++) {
        int lin = tid + it * 256;               // 4096 float4 tiles of B
        int p = lin >> 6, k4 = (lin & 63) << 2;
        float4 v = *(const float4*)&g_AB[(j0 + p) * 512 + 256 + k4];
        *(float4*)&Bsm[p * BSP + k4] = v;
    }
    Asm[tid] = g_AB[i * 512 + tid] + b1[tid];

    int ps = tid & 15, ns = tid >> 4;           // thread (pair-group, n-group)
    unsigned long long acc2[32];                // 4 pairs x 16 n, packed f32x2
#pragma unroll
    for (int q = 0; q < 32; q++) acc2[q] = 0ull;
    int zkk = tid & 15, zp0 = (tid >> 4) << 2;

    for (int kc = 0; kc < 16; kc++) {
        int K0 = kc << 4;
        __syncthreads();
#pragma unroll
        for (int it = 0; it < 4; it++) {
            int kk = (tid >> 6) + (it << 2);
            int n4 = (tid & 63) << 2;
            *(float4*)&w2sm[kk * 256 + n4] = *(const float4*)&g_W2T[(K0 + kk) * 256 + n4];
        }
        {
            float a_ = Asm[K0 + zkk];
            float4 zv;
            float v0 = a_ + Bsm[(zp0 + 0) * BSP + K0 + zkk]; zv.x = fmaxf(v0, 0.01f * v0);
            float v1 = a_ + Bsm[(zp0 + 1) * BSP + K0 + zkk]; zv.y = fmaxf(v1, 0.01f * v1);
            float v2 = a_ + Bsm[(zp0 + 2) * BSP + K0 + zkk]; zv.z = fmaxf(v2, 0.01f * v2);
            float v3 = a_ + Bsm[(zp0 + 3) * BSP + K0 + zkk]; zv.w = fmaxf(v3, 0.01f * v3);
            *(float4*)&zsm[zkk * ZSP + zp0] = zv;
        }
        __syncthreads();
#pragma unroll
        for (int kk = 0; kk < 16; kk++) {
            float4 z4 = *(const float4*)&zsm[kk * ZSP + (ps << 2)];
            const float* wr = &w2sm[kk * 256 + (ns << 4)];
            unsigned long long wv2[8];
#pragma unroll
            for (int u = 0; u < 4; u++) {
                ulonglong2 t2 = *(const ulonglong2*)&wr[u * 4];
                wv2[u * 2] = t2.x; wv2[u * 2 + 1] = t2.y;
            }
            float zz[4] = {z4.x, z4.y, z4.z, z4.w};
#pragma unroll
            for (int q = 0; q < 4; q++) {
                unsigned long long zq;
                asm("mov.b64 %0, {%1, %1};" : "=l"(zq) : "f"(zz[q]));
#pragma unroll
                for (int j2 = 0; j2 < 8; j2++)
                    asm("fma.rn.f32x2 %0, %1, %2, %0;"
                        : "+l"(acc2[q * 8 + j2]) : "l"(zq), "l"(wv2[j2]));
            }
        }
    }
    __syncthreads();
    // epilogue: y = leaky(acc + b2) -> ysm (reuse Bsm); WfT -> w2sm region
    {
        float* ysm = Bsm;
        float2 b2v[8];
#pragma unroll
        for (int j2 = 0; j2 < 8; j2++)
            b2v[j2] = *(const float2*)&b2[(ns << 4) + j2 * 2];
#pragma unroll
        for (int q = 0; q < 4; q++) {
            int p = (ps << 2) + q;
#pragma unroll
            for (int j2 = 0; j2 < 8; j2++) {
                float lo, hi;
                asm("mov.b64 {%0, %1}, %2;" : "=f"(lo), "=f"(hi) : "l"(acc2[q * 8 + j2]));
                lo += b2v[j2].x; hi += b2v[j2].y;
                float2 yv;
                yv.x = fmaxf(lo, 0.01f * lo);
                yv.y = fmaxf(hi, 0.01f * hi);
                *(float2*)&ysm[p * BSP + (ns << 4) + j2 * 2] = yv;
            }
        }
        float* wfT = w2sm;                      // [256][16] transposed Wf
#pragma unroll
        for (int it = 0; it < 16; it++) {
            int idx = tid + it * 256;           // 4096
            int r = idx >> 8, n = idx & 255;
            wfT[n * 16 + r] = Wf[r * 256 + n];
        }
        __syncthreads();
        // out[(i*384 + j0+p)*16 + r] = bf[r] + sum_n ysm[p][n] * WfT[n][r]
#pragma unroll
        for (int it = 0; it < 4; it++) {
            int oidx = tid + it * 256;          // 1024 outputs
            int p = oidx >> 4, r = oidx & 15;
            float acc = bf[r];
            for (int n = 0; n < 256; n += 4) {
                float4 y4 = *(const float4*)&ysm[p * BSP + n];
                acc = fmaf(y4.x, wfT[(n + 0) * 16 + r], acc);
                acc = fmaf(y4.y, wfT[(n + 1) * 16 + r], acc);
                acc = fmaf(y4.z, wfT[(n + 2) * 16 + r], acc);
                acc = fmaf(y4.w, wfT[(n + 3) * 16 + r], acc);
            }
            out[(i * NSEQ + j0 + p) * 16 + r] = acc;
        }
    }
}

// ---------------- launch ------------------------------------------------------
extern "C" void kernel_launch(void* const* d_in, const int* in_sizes, int n_in,
                              void* d_out, int out_size) {
    const int*   wid   = (const int*)d_in[0];
    const int*   tyid  = (const int*)d_in[1];
    const float* etab  = (const float*)d_in[2];
    const float* ttab  = (const float*)d_in[3];
    const float* Wih_f = (const float*)d_in[4];
    const float* Whh_f = (const float*)d_in[5];
    const float* bih_f = (const float*)d_in[6];
    const float* bhh_f = (const float*)d_in[7];
    const float* Wih_b = (const float*)d_in[8];
    const float* Whh_b = (const float*)d_in[9];
    const float* bih_b = (const float*)d_in[10];
    const float* bhh_b = (const float*)d_in[11];
    const float* W1    = (const float*)d_in[12];
    const float* b1    = (const float*)d_in[13];
    const float* W2    = (const float*)d_in[14];
    const float* b2    = (const float*)d_in[15];
    const float* Wf    = (const float*)d_in[16];
    const float* bf    = (const float*)d_in[17];
    float* out = (float*)d_out;

    cudaFuncSetAttribute(pair_kernel,
                         cudaFuncAttributeMaxDynamicSharedMemorySize, 90112);

    embed_kernel<<<NSEQ, 352>>>(wid, tyid, etab, ttab);
    gx_kernel<<<dim3(128, 2), 384>>>(Wih_f, bih_f, bhh_f, Wih_b, bih_b, bhh_b);
    w2t_kernel<<<256, 256>>>(W2);
    lstm_kernel<<<16, 256>>>(Whh_f, Whh_b);
    ab_kernel<<<64, 384>>>(W1);
    pair_kernel<<<dim3(6, NSEQ), 256, SM_TOT * 4>>>(b1, b2, Wf, bf, out);
}